// round 16
// baseline (speedup 1.0000x reference)
#include <cuda_runtime.h>
#include <cuda_bf16.h>
#include <cuda_fp16.h>
#include <cstdint>

// ===========================================================================
// Problem constants
// ===========================================================================
#define E_DIM  1024
#define FF_DIM 4096
#define NB     4
#define SEQ    2048
#define NROWS  (NB * SEQ)        // 8192
#define EPSV   1e-5f

// GEMM tiling: CTA 128x256, K-step 64, 512 threads (16 warps of 64x32)
#define BM 128
#define BN 256
#define BK 64
#define NTHREADS 512
#define TILE_A   (128 * BK * 2)               // 16 KB (A hi or lo)
#define TILE_BB  (256 * BK * 2)               // 32 KB (B hi or lo)
#define STAGE_B  (2 * TILE_A + 2 * TILE_BB)   // 96 KB
#define SMEM_GEMM (2 * STAGE_B)               // 192 KB

// fp16 FFN path: A split hi/lo, B single
#define FSTAGE_B (2 * TILE_A + TILE_BB)       // 64 KB
#define SMEM_F16 (2 * FSTAGE_B)               // 128 KB

typedef __nv_bfloat16 bf;
typedef __half hf;

// ===========================================================================
// Scratch
// ===========================================================================
static __device__ __align__(1024) unsigned char g_buf[671088640];

// ===========================================================================
// PTX helpers (all sm_80-era: legal under compute_100)
// ===========================================================================
__device__ __forceinline__ uint32_t smem_u32(const void* p) {
    uint32_t a;
    asm("{ .reg .u64 t; cvta.to.shared.u64 t, %1; cvt.u32.u64 %0, t; }" : "=r"(a) : "l"(p));
    return a;
}
#define CP16(s, g) \
    asm volatile("cp.async.cg.shared.global [%0], [%1], 16;" :: "r"(s), "l"(g) : "memory")
#define CP_COMMIT() asm volatile("cp.async.commit_group;" ::: "memory")
#define CP_WAIT0()  asm volatile("cp.async.wait_group 0;" ::: "memory")

__device__ __forceinline__ void ldm4(uint32_t* r, uint32_t addr) {
    asm volatile("ldmatrix.sync.aligned.m8n8.x4.shared.b16 {%0,%1,%2,%3}, [%4];"
        : "=r"(r[0]), "=r"(r[1]), "=r"(r[2]), "=r"(r[3]) : "r"(addr));
}
__device__ __forceinline__ void mma_bf(float* d, const uint32_t* a, const uint32_t* b) {
    asm volatile("mma.sync.aligned.m16n8k16.row.col.f32.bf16.bf16.f32 "
        "{%0,%1,%2,%3}, {%4,%5,%6,%7}, {%8,%9}, {%0,%1,%2,%3};"
        : "+f"(d[0]), "+f"(d[1]), "+f"(d[2]), "+f"(d[3])
        : "r"(a[0]), "r"(a[1]), "r"(a[2]), "r"(a[3]), "r"(b[0]), "r"(b[1]));
}
__device__ __forceinline__ void mma_hf(float* d, const uint32_t* a, const uint32_t* b) {
    asm volatile("mma.sync.aligned.m16n8k16.row.col.f32.f16.f16.f32 "
        "{%0,%1,%2,%3}, {%4,%5,%6,%7}, {%8,%9}, {%0,%1,%2,%3};"
        : "+f"(d[0]), "+f"(d[1]), "+f"(d[2]), "+f"(d[3])
        : "r"(a[0]), "r"(a[1]), "r"(a[2]), "r"(a[3]), "r"(b[0]), "r"(b[1]));
}

// smem tile row: 64 halfwords = 128 B; XOR-8 swizzle on 16B chunks
#define SWZ(r, kc) ((uint32_t)((r) * 128 + ((((kc) ^ ((r) & 7))) << 4)))

// ===========================================================================
// split helpers
// ===========================================================================
union BF2U { __nv_bfloat162 h; uint32_t u; };
__device__ __forceinline__ void split_pair(float a, float b, uint32_t& hp, uint32_t& lp)
{
    BF2U h; h.h = __floats2bfloat162_rn(a, b);
    BF2U l; l.h = __floats2bfloat162_rn(a - __low2float(h.h), b - __high2float(h.h));
    hp = h.u; lp = l.u;
}
union HF2U { __half2 h; uint32_t u; };
__device__ __forceinline__ void split_pair_h(float a, float b, uint32_t& hp, uint32_t& lp)
{
    HF2U h; h.h = __floats2half2_rn(a, b);
    HF2U l; l.h = __floats2half2_rn(a - __low2float(h.h), b - __high2float(h.h));
    hp = h.u; lp = l.u;
}

// ===========================================================================
// bf16 3-MMA GEMM core. CTA 128x256, 16 warps of 64x32, 512 threads.
// Two-pass A fragments: [Ah x (Bh,Bl)] then reload Al in place [Al x Bh].
// 2-stage pipeline, one __syncthreads per K-iter.
// ===========================================================================
template<bool SPLIT_OUT, bool RELU>
__device__ __forceinline__ void gemm_core(
    const bf* pAh, const bf* pAl, const bf* pBh, const bf* pBl,
    const float* bias, float* Cf, bf* Ch, bf* Cl,
    int N, int K, int m0, int n0, uint32_t sb0)
{
    const int tid  = threadIdx.x;
    const int lane = tid & 31;
    const int warp = tid >> 5;          // 0..15
    const int wm   = (warp >> 3) * 64;  // 0 / 64
    const int wn   = (warp & 7) * 32;   // 0..224
    const int nk   = K / BK;

    auto load_stage = [&](int s, int i) {
        const uint32_t base = sb0 + s * STAGE_B;
        const int k0 = i * BK;
        #pragma unroll
        for (int j = 0; j < 2; j++) {                 // A: 1024 chunks / half
            const int idx = tid + j * NTHREADS;
            const int r  = idx >> 3;
            const int kc = idx & 7;
            const uint32_t so = SWZ(r, kc);
            const size_t go = (size_t)r * K + k0 + kc * 8;
            CP16(base + so,          pAh + go);
            CP16(base + TILE_A + so, pAl + go);
        }
        #pragma unroll
        for (int j = 0; j < 4; j++) {                 // B: 2048 chunks / half
            const int idx = tid + j * NTHREADS;
            const int r  = idx >> 3;
            const int kc = idx & 7;
            const uint32_t so = SWZ(r, kc);
            const size_t go = (size_t)r * K + k0 + kc * 8;
            CP16(base + 2 * TILE_A + so,           pBh + go);
            CP16(base + 2 * TILE_A + TILE_BB + so, pBl + go);
        }
    };

    float acc[4][4][4];
    #pragma unroll
    for (int m = 0; m < 4; m++)
        #pragma unroll
        for (int n = 0; n < 4; n++)
            #pragma unroll
            for (int q = 0; q < 4; q++) acc[m][n][q] = 0.f;

    load_stage(0, 0);
    CP_COMMIT();

    for (int i = 0; i < nk; i++) {
        const int s = i & 1;
        CP_WAIT0();
        __syncthreads();
        if (i + 1 < nk) { load_stage(s ^ 1, i + 1); CP_COMMIT(); }

        const uint32_t Ahb = sb0 + s * STAGE_B;
        const uint32_t Alb = Ahb + TILE_A;
        const uint32_t Bhb = Ahb + 2 * TILE_A;
        const uint32_t Blb = Ahb + 2 * TILE_A + TILE_BB;

        #pragma unroll
        for (int ks = 0; ks < 4; ks++) {
            const int lrow = lane & 15;
            const int kc   = ks * 2 + (lane >> 4);

            // B fragments: 32 cols = 2 ldm4 per half
            uint32_t bh[4][2], bl[4][2];
            #pragma unroll
            for (int g = 0; g < 2; g++) {
                const int r = wn + g * 16 + lrow;
                uint32_t t4[4], u4[4];
                ldm4(t4, Bhb + SWZ(r, kc));
                ldm4(u4, Blb + SWZ(r, kc));
                bh[g*2+0][0] = t4[0]; bh[g*2+0][1] = t4[2];
                bh[g*2+1][0] = t4[1]; bh[g*2+1][1] = t4[3];
                bl[g*2+0][0] = u4[0]; bl[g*2+0][1] = u4[2];
                bl[g*2+1][0] = u4[1]; bl[g*2+1][1] = u4[3];
            }

            // Pass 1: Ah x (Bh + Bl)
            uint32_t af[4][4];
            #pragma unroll
            for (int f = 0; f < 4; f++)
                ldm4(af[f], Ahb + SWZ(wm + f * 16 + lrow, kc));
            #pragma unroll
            for (int m = 0; m < 4; m++)
                #pragma unroll
                for (int nn = 0; nn < 4; nn++) {
                    mma_bf(acc[m][nn], af[m], bh[nn]);
                    mma_bf(acc[m][nn], af[m], bl[nn]);
                }
            // Pass 2: Al x Bh (reuse af registers)
            #pragma unroll
            for (int f = 0; f < 4; f++)
                ldm4(af[f], Alb + SWZ(wm + f * 16 + lrow, kc));
            #pragma unroll
            for (int m = 0; m < 4; m++)
                #pragma unroll
                for (int nn = 0; nn < 4; nn++)
                    mma_bf(acc[m][nn], af[m], bh[nn]);
        }
    }

    const int qr = lane >> 2;
    const int qc = (lane & 3) * 2;

    #pragma unroll
    for (int m = 0; m < 4; m++) {
        #pragma unroll
        for (int n = 0; n < 4; n++) {
            const int row = m0 + wm + m * 16 + qr;
            const int col = n0 + wn + n * 8 + qc;
            float v0 = acc[m][n][0], v1 = acc[m][n][1];
            float v2 = acc[m][n][2], v3 = acc[m][n][3];
            if (bias) {
                const float b0 = __ldg(&bias[col]), b1 = __ldg(&bias[col + 1]);
                v0 += b0; v1 += b1; v2 += b0; v3 += b1;
            }
            if (RELU) {
                v0 = fmaxf(v0, 0.f); v1 = fmaxf(v1, 0.f);
                v2 = fmaxf(v2, 0.f); v3 = fmaxf(v3, 0.f);
            }
            const size_t o0 = (size_t)row * N + col;
            const size_t o1 = (size_t)(row + 8) * N + col;
            if (!SPLIT_OUT) {
                *(float2*)(Cf + o0) = make_float2(v0, v1);
                *(float2*)(Cf + o1) = make_float2(v2, v3);
            } else {
                uint32_t h0, l0, h1, l1;
                split_pair(v0, v1, h0, l0);
                split_pair(v2, v3, h1, l1);
                *(uint32_t*)(Ch + o0) = h0;
                *(uint32_t*)(Cl + o0) = l0;
                *(uint32_t*)(Ch + o1) = h1;
                *(uint32_t*)(Cl + o1) = l1;
            }
        }
    }
}

template<bool SPLIT_OUT, bool RELU>
__global__ __launch_bounds__(NTHREADS, 1)
void mma_gemm(const bf* __restrict__ Ah, const bf* __restrict__ Al,
              const bf* __restrict__ Bh, const bf* __restrict__ Bl,
              const float* __restrict__ bias, float* __restrict__ Cf,
              bf* __restrict__ Ch, bf* __restrict__ Cl,
              int N, int K, size_t sA, size_t sB, size_t sC)
{
    extern __shared__ __align__(1024) unsigned char smem[];
    const uint32_t sb0 = smem_u32(smem);
    const int m0 = blockIdx.y * BM;
    const int n0 = blockIdx.x * BN;
    const int z  = blockIdx.z;
    gemm_core<SPLIT_OUT, RELU>(
        Ah + (size_t)z * sA + (size_t)m0 * K,
        Al + (size_t)z * sA + (size_t)m0 * K,
        Bh + (size_t)z * sB + (size_t)n0 * K,
        Bl + (size_t)z * sB + (size_t)n0 * K,
        bias,
        Cf ? Cf + (size_t)z * sC : nullptr,
        Ch ? Ch + (size_t)z * sC : nullptr,
        Cl ? Cl + (size_t)z * sC : nullptr,
        N, K, m0, n0, sb0);
}

// Fused QKV (bf16 3-MMA): blockIdx.z selects {Q,K,V}.
__global__ __launch_bounds__(NTHREADS, 1)
void qkv_gemm(const bf* __restrict__ Ah, const bf* __restrict__ Al,
              const bf* __restrict__ Wqh, const bf* __restrict__ Wql,
              const bf* __restrict__ Wkh, const bf* __restrict__ Wkl,
              const bf* __restrict__ Wvh, const bf* __restrict__ Wvl,
              const float* __restrict__ bq, const float* __restrict__ bk,
              const float* __restrict__ bv,
              bf* __restrict__ Qh, bf* __restrict__ Ql,
              bf* __restrict__ Kh, bf* __restrict__ Kl,
              bf* __restrict__ Vh, bf* __restrict__ Vl)
{
    extern __shared__ __align__(1024) unsigned char smem[];
    const uint32_t sb0 = smem_u32(smem);
    const int m0 = blockIdx.y * BM;
    const int n0 = blockIdx.x * BN;
    const int z  = blockIdx.z;

    const bf* Bh; const bf* Bl; const float* bias; bf* Ch; bf* Cl;
    if (z == 0)      { Bh = Wqh; Bl = Wql; bias = bq; Ch = Qh; Cl = Ql; }
    else if (z == 1) { Bh = Wkh; Bl = Wkl; bias = bk; Ch = Kh; Cl = Kl; }
    else             { Bh = Wvh; Bl = Wvl; bias = bv; Ch = Vh; Cl = Vl; }

    gemm_core<true, false>(
        Ah + (size_t)m0 * E_DIM, Al + (size_t)m0 * E_DIM,
        Bh + (size_t)n0 * E_DIM, Bl + (size_t)n0 * E_DIM,
        bias, nullptr, Ch, Cl, E_DIM, E_DIM, m0, n0, sb0);
}

// ===========================================================================
// fp16 2-MMA GEMM (FFN path): A split fp16 hi/lo, B single fp16.
// Two-pass A frags. CTA 128x256, 16 warps of 64x32, 512 threads.
// ===========================================================================
template<bool SPLIT_OUT, bool RELU>
__global__ __launch_bounds__(NTHREADS, 1)
void f16_gemm(const hf* __restrict__ Ah, const hf* __restrict__ Al,
              const hf* __restrict__ B,
              const float* __restrict__ bias, float* __restrict__ Cf,
              hf* __restrict__ Ch, hf* __restrict__ Cl,
              int N, int K)
{
    extern __shared__ __align__(1024) unsigned char smem[];
    const uint32_t sb0 = smem_u32(smem);
    const int tid  = threadIdx.x;
    const int lane = tid & 31;
    const int warp = tid >> 5;
    const int wm   = (warp >> 3) * 64;
    const int wn   = (warp & 7) * 32;
    const int m0   = blockIdx.y * BM;
    const int n0   = blockIdx.x * BN;
    const int nk   = K / BK;

    const hf* pAh = Ah + (size_t)m0 * K;
    const hf* pAl = Al + (size_t)m0 * K;
    const hf* pB  = B  + (size_t)n0 * K;

    auto load_stage = [&](int s, int i) {
        const uint32_t base = sb0 + s * FSTAGE_B;
        const int k0 = i * BK;
        #pragma unroll
        for (int j = 0; j < 2; j++) {
            const int idx = tid + j * NTHREADS;
            const int r  = idx >> 3;
            const int kc = idx & 7;
            const uint32_t so = SWZ(r, kc);
            const size_t go = (size_t)r * K + k0 + kc * 8;
            CP16(base + so,          pAh + go);
            CP16(base + TILE_A + so, pAl + go);
        }
        #pragma unroll
        for (int j = 0; j < 4; j++) {
            const int idx = tid + j * NTHREADS;
            const int r  = idx >> 3;
            const int kc = idx & 7;
            const uint32_t so = SWZ(r, kc);
            const size_t go = (size_t)r * K + k0 + kc * 8;
            CP16(base + 2 * TILE_A + so, pB + go);
        }
    };

    float acc[4][4][4];
    #pragma unroll
    for (int m = 0; m < 4; m++)
        #pragma unroll
        for (int n = 0; n < 4; n++)
            #pragma unroll
            for (int q = 0; q < 4; q++) acc[m][n][q] = 0.f;

    load_stage(0, 0);
    CP_COMMIT();

    for (int i = 0; i < nk; i++) {
        const int s = i & 1;
        CP_WAIT0();
        __syncthreads();
        if (i + 1 < nk) { load_stage(s ^ 1, i + 1); CP_COMMIT(); }

        const uint32_t Ahb = sb0 + s * FSTAGE_B;
        const uint32_t Alb = Ahb + TILE_A;
        const uint32_t Bb  = Ahb + 2 * TILE_A;

        #pragma unroll
        for (int ks = 0; ks < 4; ks++) {
            const int lrow = lane & 15;
            const int kc   = ks * 2 + (lane >> 4);

            uint32_t bb[4][2];
            #pragma unroll
            for (int g = 0; g < 2; g++) {
                const int r = wn + g * 16 + lrow;
                uint32_t t4[4];
                ldm4(t4, Bb + SWZ(r, kc));
                bb[g*2+0][0] = t4[0]; bb[g*2+0][1] = t4[2];
                bb[g*2+1][0] = t4[1]; bb[g*2+1][1] = t4[3];
            }

            uint32_t af[4][4];
            #pragma unroll
            for (int f = 0; f < 4; f++)
                ldm4(af[f], Ahb + SWZ(wm + f * 16 + lrow, kc));
            #pragma unroll
            for (int m = 0; m < 4; m++)
                #pragma unroll
                for (int nn = 0; nn < 4; nn++)
                    mma_hf(acc[m][nn], af[m], bb[nn]);
            #pragma unroll
            for (int f = 0; f < 4; f++)
                ldm4(af[f], Alb + SWZ(wm + f * 16 + lrow, kc));
            #pragma unroll
            for (int m = 0; m < 4; m++)
                #pragma unroll
                for (int nn = 0; nn < 4; nn++)
                    mma_hf(acc[m][nn], af[m], bb[nn]);
        }
    }

    const int qr = lane >> 2;
    const int qc = (lane & 3) * 2;

    #pragma unroll
    for (int m = 0; m < 4; m++) {
        #pragma unroll
        for (int n = 0; n < 4; n++) {
            const int row = m0 + wm + m * 16 + qr;
            const int col = n0 + wn + n * 8 + qc;
            float v0 = acc[m][n][0], v1 = acc[m][n][1];
            float v2 = acc[m][n][2], v3 = acc[m][n][3];
            if (bias) {
                const float b0 = __ldg(&bias[col]), b1 = __ldg(&bias[col + 1]);
                v0 += b0; v1 += b1; v2 += b0; v3 += b1;
            }
            if (RELU) {
                v0 = fmaxf(v0, 0.f); v1 = fmaxf(v1, 0.f);
                v2 = fmaxf(v2, 0.f); v3 = fmaxf(v3, 0.f);
            }
            const size_t o0 = (size_t)row * N + col;
            const size_t o1 = (size_t)(row + 8) * N + col;
            if (!SPLIT_OUT) {
                *(float2*)(Cf + o0) = make_float2(v0, v1);
                *(float2*)(Cf + o1) = make_float2(v2, v3);
            } else {
                uint32_t h0, l0, h1, l1;
                split_pair_h(v0, v1, h0, l0);
                split_pair_h(v2, v3, h1, l1);
                *(uint32_t*)(Ch + o0) = h0;
                *(uint32_t*)(Cl + o0) = l0;
                *(uint32_t*)(Ch + o1) = h1;
                *(uint32_t*)(Cl + o1) = l1;
            }
        }
    }
}

// ===========================================================================
// fp32 flat -> bf16 hi/lo
// ===========================================================================
__global__ __launch_bounds__(256)
void split_k(const float4* __restrict__ in, uint2* __restrict__ oh, uint2* __restrict__ ol, int n4)
{
    int i = blockIdx.x * 256 + threadIdx.x;
    if (i >= n4) return;
    float4 v = in[i];
    uint2 h, l;
    split_pair(v.x, v.y, h.x, l.x);
    split_pair(v.z, v.w, h.y, l.y);
    oh[i] = h; ol[i] = l;
}

// ===========================================================================
// ALL weight transposes in ONE launch.
// ===========================================================================
__global__ __launch_bounds__(256)
void tsplit_all_k(const float* __restrict__ Wq, const float* __restrict__ Wk,
                  const float* __restrict__ Wv, const float* __restrict__ Wo,
                  const float* __restrict__ W1, const float* __restrict__ W2,
                  bf* __restrict__ Wqh, bf* __restrict__ Wql,
                  bf* __restrict__ Wkh, bf* __restrict__ Wkl,
                  bf* __restrict__ Wvh, bf* __restrict__ Wvl,
                  bf* __restrict__ Woh, bf* __restrict__ Wol,
                  hf* __restrict__ W1t, hf* __restrict__ W2t)
{
    __shared__ float t[32][33];
    const int idx = blockIdx.x;
    const int tx = threadIdx.x & 31, ty = threadIdx.x >> 5;

    const float* in; int R, C, mode; bf* oh = nullptr; bf* ol = nullptr; hf* of = nullptr;
    int r0, c0;
    if (idx < 4096) {
        const int w = idx >> 10, tt = idx & 1023;
        c0 = (tt & 31) * 32; r0 = (tt >> 5) * 32;
        R = E_DIM; C = E_DIM; mode = 0;
        if (w == 0)      { in = Wq; oh = Wqh; ol = Wql; }
        else if (w == 1) { in = Wk; oh = Wkh; ol = Wkl; }
        else if (w == 2) { in = Wv; oh = Wvh; ol = Wvl; }
        else             { in = Wo; oh = Woh; ol = Wol; }
    } else if (idx < 8192) {
        const int tt = idx - 4096;
        c0 = (tt & 127) * 32; r0 = (tt >> 7) * 32;
        in = W1; R = E_DIM; C = FF_DIM; mode = 1; of = W1t;
    } else {
        const int tt = idx - 8192;
        c0 = (tt & 31) * 32; r0 = (tt >> 5) * 32;
        in = W2; R = FF_DIM; C = E_DIM; mode = 1; of = W2t;
    }

    #pragma unroll
    for (int i = 0; i < 4; i++)
        t[ty + i * 8][tx] = in[(size_t)(r0 + ty + i * 8) * C + c0 + tx];
    __syncthreads();
    #pragma unroll
    for (int i = 0; i < 4; i++) {
        const int orow = c0 + ty + i * 8, oc = r0 + tx;
        float v = t[tx][ty + i * 8];
        if (mode == 0) {
            bf h = __float2bfloat16(v);
            oh[(size_t)orow * R + oc] = h;
            ol[(size_t)orow * R + oc] = __float2bfloat16(v - __bfloat162float(h));
        } else {
            of[(size_t)orow * R + oc] = __float2half_rn(v);
        }
    }
}

// bf16 pair [z][R][C] -> transposed [z][C][R]  (V hi/lo)
__global__ __launch_bounds__(256)
void t_bf_k(const bf* __restrict__ ih, const bf* __restrict__ il,
            bf* __restrict__ oh, bf* __restrict__ ol, int R, int C)
{
    __shared__ bf th[32][33];
    __shared__ bf tl[32][33];
    const size_t zo = (size_t)blockIdx.z * R * C;
    const int r0 = blockIdx.y * 32, c0 = blockIdx.x * 32;
    const int tx = threadIdx.x & 31, ty = threadIdx.x >> 5;
    #pragma unroll
    for (int i = 0; i < 4; i++) {
        const size_t gi = zo + (size_t)(r0 + ty + i * 8) * C + c0 + tx;
        th[ty + i * 8][tx] = ih[gi];
        tl[ty + i * 8][tx] = il[gi];
    }
    __syncthreads();
    #pragma unroll
    for (int i = 0; i < 4; i++) {
        const int orow = c0 + ty + i * 8, oc = r0 + tx;
        const size_t go = zo + (size_t)orow * R + oc;
        oh[go] = th[tx][ty + i * 8];
        ol[go] = tl[tx][ty + i * 8];
    }
}

// ===========================================================================
// row softmax (2048 cols) -> split bf16
// ===========================================================================
__global__ __launch_bounds__(256)
void softmax_k(const float* __restrict__ S, bf* __restrict__ ph, bf* __restrict__ pl)
{
    const size_t rb = (size_t)blockIdx.x * SEQ;
    const int tid = threadIdx.x;
    __shared__ float red[256];
    float4 a = *(const float4*)(S + rb + tid * 8);
    float4 b = *(const float4*)(S + rb + tid * 8 + 4);
    float r[8] = {a.x, a.y, a.z, a.w, b.x, b.y, b.z, b.w};
    float m = -1e30f;
    #pragma unroll
    for (int i = 0; i < 8; i++) m = fmaxf(m, r[i]);
    red[tid] = m; __syncthreads();
    #pragma unroll
    for (int s = 128; s > 0; s >>= 1) { if (tid < s) red[tid] = fmaxf(red[tid], red[tid + s]); __syncthreads(); }
    m = red[0]; __syncthreads();
    float sum = 0.f;
    #pragma unroll
    for (int i = 0; i < 8; i++) { r[i] = __expf(r[i] - m); sum += r[i]; }
    red[tid] = sum; __syncthreads();
    #pragma unroll
    for (int s = 128; s > 0; s >>= 1) { if (tid < s) red[tid] += red[tid + s]; __syncthreads(); }
    const float inv = 1.f / red[0];
    uint32_t hp[4], lp[4];
    #pragma unroll
    for (int q = 0; q < 4; q++) split_pair(r[2*q] * inv, r[2*q+1] * inv, hp[q], lp[q]);
    *(uint4*)(ph + rb + tid * 8) = make_uint4(hp[0], hp[1], hp[2], hp[3]);
    *(uint4*)(pl + rb + tid * 8) = make_uint4(lp[0], lp[1], lp[2], lp[3]);
}

// ===========================================================================
// out = LN(a+b)*g + beta  (+ optional fp16 hi/lo split emit for FFN)
// ===========================================================================
template<bool WSPLIT>
__global__ __launch_bounds__(256)
void add_ln_k(const float* __restrict__ a, const float* __restrict__ b,
              const float* __restrict__ g, const float* __restrict__ beta,
              float* __restrict__ out, hf* __restrict__ oh, hf* __restrict__ ol)
{
    const size_t base = (size_t)blockIdx.x * E_DIM;
    const int tid = threadIdx.x, c = tid * 4;
    __shared__ float r1[256], r2[256];
    float4 va = *(const float4*)(a + base + c);
    float4 vb = *(const float4*)(b + base + c);
    float v[4] = {va.x + vb.x, va.y + vb.y, va.z + vb.z, va.w + vb.w};
    float s = 0.f, sq = 0.f;
    #pragma unroll
    for (int i = 0; i < 4; i++) { s += v[i]; sq += v[i] * v[i]; }
    r1[tid] = s; r2[tid] = sq; __syncthreads();
    #pragma unroll
    for (int st = 128; st > 0; st >>= 1) {
        if (tid < st) { r1[tid] += r1[tid + st]; r2[tid] += r2[tid + st]; }
        __syncthreads();
    }
    const float mu = r1[0] * (1.f / E_DIM);
    const float inv = rsqrtf(r2[0] * (1.f / E_DIM) - mu * mu + EPSV);
    float4 g4 = *(const float4*)(g + c);
    float4 b4 = *(const float4*)(beta + c);
    float o[4] = {(v[0]-mu)*inv*g4.x + b4.x, (v[1]-mu)*inv*g4.y + b4.y,
                  (v[2]-mu)*inv*g4.z + b4.z, (v[3]-mu)*inv*g4.w + b4.w};
    *(float4*)(out + base + c) = make_float4(o[0], o[1], o[2], o[3]);
    if (WSPLIT) {
        uint2 h, l;
        split_pair_h(o[0], o[1], h.x, l.x);
        split_pair_h(o[2], o[3], h.y, l.y);
        *(uint2*)(oh + base + c) = h;
        *(uint2*)(ol + base + c) = l;
    }
}

// ===========================================================================
// Host
// ===========================================================================
extern "C" void kernel_launch(void* const* d_in, const int* in_sizes, int n_in,
                              void* d_out, int out_size)
{
    (void)in_sizes; (void)n_in; (void)out_size;
    const float* src = (const float*)d_in[0];
    const float* Wq = (const float*)d_in[1];  const float* bq = (const float*)d_in[2];
    const float* Wk = (const float*)d_in[3];  const float* bk = (const float*)d_in[4];
    const float* Wv = (const float*)d_in[5];  const float* bv = (const float*)d_in[6];
    const float* Wo = (const float*)d_in[7];  const float* bo = (const float*)d_in[8];
    const float* W1 = (const float*)d_in[9];  const float* b1 = (const float*)d_in[10];
    const float* W2 = (const float*)d_in[11]; const float* b2 = (const float*)d_in[12];
    const float* g1 = (const float*)d_in[13]; const float* be1 = (const float*)d_in[14];
    const float* g2 = (const float*)d_in[15]; const float* be2 = (const float*)d_in[16];
    float* out = (float*)d_out;

    unsigned char* base = nullptr;
    cudaGetSymbolAddress((void**)&base, g_buf);
    size_t cur = 0;
    auto carve = [&](size_t bytes) { unsigned char* p = base + cur; cur += (bytes + 255) & ~(size_t)255; return p; };

    const size_t RE = (size_t)NROWS * E_DIM, RFF = (size_t)NROWS * FF_DIM;
    const size_t SS = (size_t)NB * SEQ * SEQ;
    const size_t WEE = (size_t)E_DIM * E_DIM, WEF = (size_t)E_DIM * FF_DIM;

    float* S_  = (float*)carve(SS * 4);
    float* tmp = (float*)carve(RE * 4);
    float* x   = (float*)carve(RE * 4);
    bf* srch = (bf*)carve(RE*2);  bf* srcl = (bf*)carve(RE*2);
    bf* Qh = (bf*)carve(RE*2);    bf* Ql = (bf*)carve(RE*2);
    bf* Kh = (bf*)carve(RE*2);    bf* Kl = (bf*)carve(RE*2);
    bf* Vh = (bf*)carve(RE*2);    bf* Vl = (bf*)carve(RE*2);
    bf* Vth = (bf*)carve(RE*2);   bf* Vtl = (bf*)carve(RE*2);
    bf* Ph = (bf*)carve(SS*2);    bf* Pl = (bf*)carve(SS*2);
    bf* ath = (bf*)carve(RE*2);   bf* atl = (bf*)carve(RE*2);
    hf* xh = (hf*)carve(RE*2);    hf* xl = (hf*)carve(RE*2);
    hf* ffh = (hf*)carve(RFF*2);  hf* ffl = (hf*)carve(RFF*2);
    bf* Wqh = (bf*)carve(WEE*2);  bf* Wql = (bf*)carve(WEE*2);
    bf* Wkh = (bf*)carve(WEE*2);  bf* Wkl = (bf*)carve(WEE*2);
    bf* Wvh = (bf*)carve(WEE*2);  bf* Wvl = (bf*)carve(WEE*2);
    bf* Woh = (bf*)carve(WEE*2);  bf* Wol = (bf*)carve(WEE*2);
    hf* W1t = (hf*)carve(WEF*2);
    hf* W2t = (hf*)carve(WEF*2);

    cudaFuncSetAttribute(mma_gemm<false,false>, cudaFuncAttributeMaxDynamicSharedMemorySize, SMEM_GEMM);
    cudaFuncSetAttribute(mma_gemm<true, false>, cudaFuncAttributeMaxDynamicSharedMemorySize, SMEM_GEMM);
    cudaFuncSetAttribute(qkv_gemm,              cudaFuncAttributeMaxDynamicSharedMemorySize, SMEM_GEMM);
    cudaFuncSetAttribute(f16_gemm<true, true >, cudaFuncAttributeMaxDynamicSharedMemorySize, SMEM_F16);
    cudaFuncSetAttribute(f16_gemm<false,false>, cudaFuncAttributeMaxDynamicSharedMemorySize, SMEM_F16);

    const dim3 b256(256);
    const dim3 b512(NTHREADS);
    // Launch order: profiled index 5 = my launch #3 (scores GEMM).
    // 0: all weight transposes in one launch
    tsplit_all_k<<<12288, b256>>>(Wq, Wk, Wv, Wo, W1, W2,
                                  Wqh, Wql, Wkh, Wkl, Wvh, Wvl, Woh, Wol, W1t, W2t);
    // 1: src split
    split_k<<<(int)(RE/4/256), b256>>>((const float4*)src, (uint2*)srch, (uint2*)srcl, (int)(RE/4));
    // 2: fused QKV
    qkv_gemm<<<dim3(E_DIM/BN, NROWS/BM, 3), b512, SMEM_GEMM>>>(
        srch, srcl, Wqh, Wql, Wkh, Wkl, Wvh, Wvl, bq, bk, bv,
        Qh, Ql, Kh, Kl, Vh, Vl);
    // 3: scores  S_b = Q_b @ K_b^T   <-- ncu capture target
    mma_gemm<false,false><<<dim3(SEQ/BN, SEQ/BM, NB), b512, SMEM_GEMM>>>(
        Qh, Ql, Kh, Kl, nullptr, S_, nullptr, nullptr, SEQ, E_DIM,
        (size_t)SEQ*E_DIM, (size_t)SEQ*E_DIM, (size_t)SEQ*SEQ);
    // 4: V transpose
    t_bf_k<<<dim3(E_DIM/32, SEQ/32, NB), b256>>>(Vh, Vl, Vth, Vtl, SEQ, E_DIM);
    // 5: softmax
    softmax_k<<<NROWS, b256>>>(S_, Ph, Pl);
    // 6: attn = P_b @ V_b
    mma_gemm<true, false><<<dim3(E_DIM/BN, SEQ/BM, NB), b512, SMEM_GEMM>>>(
        Ph, Pl, Vth, Vtl, nullptr, nullptr, ath, atl, E_DIM, SEQ,
        (size_t)SEQ*SEQ, (size_t)E_DIM*SEQ, (size_t)SEQ*E_DIM);
    // 7: O projection
    mma_gemm<false,false><<<dim3(E_DIM/BN, NROWS/BM, 1), b512, SMEM_GEMM>>>(
        ath, atl, Woh, Wol, bo, tmp, nullptr, nullptr, E_DIM, E_DIM, 0, 0, 0);
    // 8: LN1 -> x (+ fp16 split)
    add_ln_k<true><<<NROWS, b256>>>(src, tmp, g1, be1, x, xh, xl);
    // 9: FFN1 (fp16 2-MMA, relu, fp16 split out)
    f16_gemm<true, true><<<dim3(FF_DIM/BN, NROWS/BM, 1), b512, SMEM_F16>>>(
        xh, xl, W1t, b1, nullptr, ffh, ffl, FF_DIM, E_DIM);
    // 10: FFN2 (fp16 2-MMA, fp32 out)
    f16_gemm<false,false><<<dim3(E_DIM/BN, NROWS/BM, 1), b512, SMEM_F16>>>(
        ffh, ffl, W2t, b2, tmp, nullptr, nullptr, E_DIM, FF_DIM);
    // 11: LN2 -> out
    add_ln_k<false><<<NROWS, b256>>>(x, tmp, g2, be2, out, nullptr, nullptr);
}

// round 17
// speedup vs baseline: 1.1445x; 1.1445x over previous
#include <cuda_runtime.h>
#include <cuda_bf16.h>
#include <cuda_fp16.h>
#include <cstdint>

// ===========================================================================
// Problem constants
// ===========================================================================
#define E_DIM  1024
#define FF_DIM 4096
#define NB     4
#define SEQ    2048
#define NROWS  (NB * SEQ)        // 8192
#define EPSV   1e-5f

// GEMM tiling: CTA 128x256, K-step 64, 256 threads (8 warps of 64x64)
#define BM 128
#define BN 256
#define BK 64
#define TILE_A   (128 * BK * 2)               // 16 KB (A hi or lo)
#define TILE_BB  (256 * BK * 2)               // 32 KB (B hi or lo)
#define STAGE_B  (2 * TILE_A + 2 * TILE_BB)   // 96 KB
#define SMEM_GEMM (2 * STAGE_B)               // 192 KB

// fp16 path: A split hi/lo, B single
#define FSTAGE_B (2 * TILE_A + TILE_BB)       // 64 KB
#define SMEM_F16 (2 * FSTAGE_B)               // 128 KB

typedef __nv_bfloat16 bf;
typedef __half hf;

// ===========================================================================
// Scratch
// ===========================================================================
static __device__ __align__(1024) unsigned char g_buf[671088640];

// ===========================================================================
// PTX helpers (all sm_80-era: legal under compute_100)
// ===========================================================================
__device__ __forceinline__ uint32_t smem_u32(const void* p) {
    uint32_t a;
    asm("{ .reg .u64 t; cvta.to.shared.u64 t, %1; cvt.u32.u64 %0, t; }" : "=r"(a) : "l"(p));
    return a;
}
#define CP16(s, g) \
    asm volatile("cp.async.cg.shared.global [%0], [%1], 16;" :: "r"(s), "l"(g) : "memory")
#define CP_COMMIT() asm volatile("cp.async.commit_group;" ::: "memory")
#define CP_WAIT0()  asm volatile("cp.async.wait_group 0;" ::: "memory")

__device__ __forceinline__ void ldm4(uint32_t* r, uint32_t addr) {
    asm volatile("ldmatrix.sync.aligned.m8n8.x4.shared.b16 {%0,%1,%2,%3}, [%4];"
        : "=r"(r[0]), "=r"(r[1]), "=r"(r[2]), "=r"(r[3]) : "r"(addr));
}
__device__ __forceinline__ void mma_bf(float* d, const uint32_t* a, const uint32_t* b) {
    asm volatile("mma.sync.aligned.m16n8k16.row.col.f32.bf16.bf16.f32 "
        "{%0,%1,%2,%3}, {%4,%5,%6,%7}, {%8,%9}, {%0,%1,%2,%3};"
        : "+f"(d[0]), "+f"(d[1]), "+f"(d[2]), "+f"(d[3])
        : "r"(a[0]), "r"(a[1]), "r"(a[2]), "r"(a[3]), "r"(b[0]), "r"(b[1]));
}
__device__ __forceinline__ void mma_hf(float* d, const uint32_t* a, const uint32_t* b) {
    asm volatile("mma.sync.aligned.m16n8k16.row.col.f32.f16.f16.f32 "
        "{%0,%1,%2,%3}, {%4,%5,%6,%7}, {%8,%9}, {%0,%1,%2,%3};"
        : "+f"(d[0]), "+f"(d[1]), "+f"(d[2]), "+f"(d[3])
        : "r"(a[0]), "r"(a[1]), "r"(a[2]), "r"(a[3]), "r"(b[0]), "r"(b[1]));
}

// smem tile row: 64 halfwords = 128 B; XOR-8 swizzle on 16B chunks
#define SWZ(r, kc) ((uint32_t)((r) * 128 + ((((kc) ^ ((r) & 7))) << 4)))

// ===========================================================================
// split helpers
// ===========================================================================
union BF2U { __nv_bfloat162 h; uint32_t u; };
__device__ __forceinline__ void split_pair(float a, float b, uint32_t& hp, uint32_t& lp)
{
    BF2U h; h.h = __floats2bfloat162_rn(a, b);
    BF2U l; l.h = __floats2bfloat162_rn(a - __low2float(h.h), b - __high2float(h.h));
    hp = h.u; lp = l.u;
}
union HF2U { __half2 h; uint32_t u; };
__device__ __forceinline__ void split_pair_h(float a, float b, uint32_t& hp, uint32_t& lp)
{
    HF2U h; h.h = __floats2half2_rn(a, b);
    HF2U l; l.h = __floats2half2_rn(a - __low2float(h.h), b - __high2float(h.h));
    hp = h.u; lp = l.u;
}

// ===========================================================================
// bf16 3-MMA GEMM core (Q/K proj + scores). CTA 128x256, 8 warps of 64x64.
// D = AhBh + AhBl + AlBh, fp32 accum. 2-stage, single sync per K-iter.
// ===========================================================================
template<bool SPLIT_OUT>
__device__ __forceinline__ void gemm_core(
    const bf* pAh, const bf* pAl, const bf* pBh, const bf* pBl,
    const float* bias, float* Cf, bf* Ch, bf* Cl,
    int N, int K, int m0, int n0, uint32_t sb0)
{
    const int tid  = threadIdx.x;
    const int lane = tid & 31;
    const int warp = tid >> 5;
    const int wm   = (warp >> 2) * 64;
    const int wn   = (warp & 3) * 64;
    const int nk   = K / BK;

    auto load_stage = [&](int s, int i) {
        const uint32_t base = sb0 + s * STAGE_B;
        const int k0 = i * BK;
        #pragma unroll
        for (int j = 0; j < 4; j++) {
            const int idx = tid + j * 256;
            const int r  = idx >> 3;
            const int kc = idx & 7;
            const uint32_t so = SWZ(r, kc);
            const size_t go = (size_t)r * K + k0 + kc * 8;
            CP16(base + so,          pAh + go);
            CP16(base + TILE_A + so, pAl + go);
        }
        #pragma unroll
        for (int j = 0; j < 8; j++) {
            const int idx = tid + j * 256;
            const int r  = idx >> 3;
            const int kc = idx & 7;
            const uint32_t so = SWZ(r, kc);
            const size_t go = (size_t)r * K + k0 + kc * 8;
            CP16(base + 2 * TILE_A + so,           pBh + go);
            CP16(base + 2 * TILE_A + TILE_BB + so, pBl + go);
        }
    };

    float acc[4][8][4];
    #pragma unroll
    for (int m = 0; m < 4; m++)
        #pragma unroll
        for (int n = 0; n < 8; n++)
            #pragma unroll
            for (int q = 0; q < 4; q++) acc[m][n][q] = 0.f;

    load_stage(0, 0);
    CP_COMMIT();

    for (int i = 0; i < nk; i++) {
        const int s = i & 1;
        CP_WAIT0();
        __syncthreads();
        if (i + 1 < nk) { load_stage(s ^ 1, i + 1); CP_COMMIT(); }

        const uint32_t Ahb = sb0 + s * STAGE_B;
        const uint32_t Alb = Ahb + TILE_A;
        const uint32_t Bhb = Ahb + 2 * TILE_A;
        const uint32_t Blb = Ahb + 2 * TILE_A + TILE_BB;

        #pragma unroll
        for (int ks = 0; ks < 4; ks++) {
            const int lrow = lane & 15;
            const int kc   = ks * 2 + (lane >> 4);

            uint32_t ah[4][4], al[4][4];
            #pragma unroll
            for (int f = 0; f < 4; f++) {
                const int r = wm + f * 16 + lrow;
                ldm4(ah[f], Ahb + SWZ(r, kc));
                ldm4(al[f], Alb + SWZ(r, kc));
            }
            #pragma unroll
            for (int half = 0; half < 2; half++) {
                uint32_t bh[4][2], bl[4][2];
                #pragma unroll
                for (int g = 0; g < 2; g++) {
                    const int r = wn + (half * 2 + g) * 16 + lrow;
                    uint32_t t4[4], u4[4];
                    ldm4(t4, Bhb + SWZ(r, kc));
                    ldm4(u4, Blb + SWZ(r, kc));
                    bh[g*2+0][0] = t4[0]; bh[g*2+0][1] = t4[2];
                    bh[g*2+1][0] = t4[1]; bh[g*2+1][1] = t4[3];
                    bl[g*2+0][0] = u4[0]; bl[g*2+0][1] = u4[2];
                    bl[g*2+1][0] = u4[1]; bl[g*2+1][1] = u4[3];
                }
                #pragma unroll
                for (int m = 0; m < 4; m++)
                    #pragma unroll
                    for (int nn = 0; nn < 4; nn++) {
                        float* a = acc[m][half * 4 + nn];
                        mma_bf(a, ah[m], bh[nn]);
                        mma_bf(a, ah[m], bl[nn]);
                        mma_bf(a, al[m], bh[nn]);
                    }
            }
        }
    }

    const int qr = lane >> 2;
    const int qc = (lane & 3) * 2;

    #pragma unroll
    for (int m = 0; m < 4; m++) {
        #pragma unroll
        for (int n = 0; n < 8; n++) {
            const int row = m0 + wm + m * 16 + qr;
            const int col = n0 + wn + n * 8 + qc;
            float v0 = acc[m][n][0], v1 = acc[m][n][1];
            float v2 = acc[m][n][2], v3 = acc[m][n][3];
            if (bias) {
                const float b0 = __ldg(&bias[col]), b1 = __ldg(&bias[col + 1]);
                v0 += b0; v1 += b1; v2 += b0; v3 += b1;
            }
            const size_t o0 = (size_t)row * N + col;
            const size_t o1 = (size_t)(row + 8) * N + col;
            if (!SPLIT_OUT) {
                *(float2*)(Cf + o0) = make_float2(v0, v1);
                *(float2*)(Cf + o1) = make_float2(v2, v3);
            } else {
                uint32_t h0, l0, h1, l1;
                split_pair(v0, v1, h0, l0);
                split_pair(v2, v3, h1, l1);
                *(uint32_t*)(Ch + o0) = h0;
                *(uint32_t*)(Cl + o0) = l0;
                *(uint32_t*)(Ch + o1) = h1;
                *(uint32_t*)(Cl + o1) = l1;
            }
        }
    }
}

template<bool SPLIT_OUT>
__global__ __launch_bounds__(256, 1)
void mma_gemm(const bf* __restrict__ Ah, const bf* __restrict__ Al,
              const bf* __restrict__ Bh, const bf* __restrict__ Bl,
              const float* __restrict__ bias, float* __restrict__ Cf,
              bf* __restrict__ Ch, bf* __restrict__ Cl,
              int N, int K, size_t sA, size_t sB, size_t sC)
{
    extern __shared__ __align__(1024) unsigned char smem[];
    const uint32_t sb0 = smem_u32(smem);
    const int m0 = blockIdx.y * BM;
    const int n0 = blockIdx.x * BN;
    const int z  = blockIdx.z;
    gemm_core<SPLIT_OUT>(
        Ah + (size_t)z * sA + (size_t)m0 * K,
        Al + (size_t)z * sA + (size_t)m0 * K,
        Bh + (size_t)z * sB + (size_t)n0 * K,
        Bl + (size_t)z * sB + (size_t)n0 * K,
        bias,
        Cf ? Cf + (size_t)z * sC : nullptr,
        Ch ? Ch + (size_t)z * sC : nullptr,
        Cl ? Cl + (size_t)z * sC : nullptr,
        N, K, m0, n0, sb0);
}

// Fused Q/K projections (bf16 3-MMA, split-out): blockIdx.z selects {Q,K}.
__global__ __launch_bounds__(256, 1)
void qk_gemm(const bf* __restrict__ Ah, const bf* __restrict__ Al,
             const bf* __restrict__ Wqh, const bf* __restrict__ Wql,
             const bf* __restrict__ Wkh, const bf* __restrict__ Wkl,
             const float* __restrict__ bq, const float* __restrict__ bk,
             bf* __restrict__ Qh, bf* __restrict__ Ql,
             bf* __restrict__ Kh, bf* __restrict__ Kl)
{
    extern __shared__ __align__(1024) unsigned char smem[];
    const uint32_t sb0 = smem_u32(smem);
    const int m0 = blockIdx.y * BM;
    const int n0 = blockIdx.x * BN;
    const int z  = blockIdx.z;

    const bf* Bh; const bf* Bl; const float* bias; bf* Ch; bf* Cl;
    if (z == 0) { Bh = Wqh; Bl = Wql; bias = bq; Ch = Qh; Cl = Ql; }
    else        { Bh = Wkh; Bl = Wkl; bias = bk; Ch = Kh; Cl = Kl; }

    gemm_core<true>(
        Ah + (size_t)m0 * E_DIM, Al + (size_t)m0 * E_DIM,
        Bh + (size_t)n0 * E_DIM, Bl + (size_t)n0 * E_DIM,
        bias, nullptr, Ch, Cl, E_DIM, E_DIM, m0, n0, sb0);
}

// ===========================================================================
// fp16 2-MMA GEMM: A split fp16 hi/lo, B single fp16. Batched via strides.
// OUTMODE: 0 = fp32, 1 = fp16 hi/lo split, 2 = fp16 single.
// ===========================================================================
template<int OUTMODE, bool RELU>
__global__ __launch_bounds__(256, 1)
void f16_gemm(const hf* __restrict__ Ah, const hf* __restrict__ Al,
              const hf* __restrict__ B,
              const float* __restrict__ bias, float* __restrict__ Cf,
              hf* __restrict__ Ch, hf* __restrict__ Cl,
              int N, int K, size_t sA, size_t sB, size_t sC)
{
    extern __shared__ __align__(1024) unsigned char smem[];
    const uint32_t sb0 = smem_u32(smem);
    const int tid  = threadIdx.x;
    const int lane = tid & 31;
    const int warp = tid >> 5;
    const int wm   = (warp >> 2) * 64;
    const int wn   = (warp & 3) * 64;
    const int m0   = blockIdx.y * BM;
    const int n0   = blockIdx.x * BN;
    const int z    = blockIdx.z;
    const int nk   = K / BK;

    const hf* pAh = Ah + (size_t)z * sA + (size_t)m0 * K;
    const hf* pAl = Al + (size_t)z * sA + (size_t)m0 * K;
    const hf* pB  = B  + (size_t)z * sB + (size_t)n0 * K;
    const size_t zoff = (size_t)z * sC;

    auto load_stage = [&](int s, int i) {
        const uint32_t base = sb0 + s * FSTAGE_B;
        const int k0 = i * BK;
        #pragma unroll
        for (int j = 0; j < 4; j++) {
            const int idx = tid + j * 256;
            const int r  = idx >> 3;
            const int kc = idx & 7;
            const uint32_t so = SWZ(r, kc);
            const size_t go = (size_t)r * K + k0 + kc * 8;
            CP16(base + so,          pAh + go);
            CP16(base + TILE_A + so, pAl + go);
        }
        #pragma unroll
        for (int j = 0; j < 8; j++) {
            const int idx = tid + j * 256;
            const int r  = idx >> 3;
            const int kc = idx & 7;
            const uint32_t so = SWZ(r, kc);
            const size_t go = (size_t)r * K + k0 + kc * 8;
            CP16(base + 2 * TILE_A + so, pB + go);
        }
    };

    float acc[4][8][4];
    #pragma unroll
    for (int m = 0; m < 4; m++)
        #pragma unroll
        for (int n = 0; n < 8; n++)
            #pragma unroll
            for (int q = 0; q < 4; q++) acc[m][n][q] = 0.f;

    load_stage(0, 0);
    CP_COMMIT();

    for (int i = 0; i < nk; i++) {
        const int s = i & 1;
        CP_WAIT0();
        __syncthreads();
        if (i + 1 < nk) { load_stage(s ^ 1, i + 1); CP_COMMIT(); }

        const uint32_t Ahb = sb0 + s * FSTAGE_B;
        const uint32_t Alb = Ahb + TILE_A;
        const uint32_t Bb  = Ahb + 2 * TILE_A;

        #pragma unroll
        for (int ks = 0; ks < 4; ks++) {
            const int lrow = lane & 15;
            const int kc   = ks * 2 + (lane >> 4);

            uint32_t ah[4][4], al[4][4];
            #pragma unroll
            for (int f = 0; f < 4; f++) {
                const int r = wm + f * 16 + lrow;
                ldm4(ah[f], Ahb + SWZ(r, kc));
                ldm4(al[f], Alb + SWZ(r, kc));
            }
            #pragma unroll
            for (int half = 0; half < 2; half++) {
                uint32_t bb[4][2];
                #pragma unroll
                for (int g = 0; g < 2; g++) {
                    const int r = wn + (half * 2 + g) * 16 + lrow;
                    uint32_t t4[4];
                    ldm4(t4, Bb + SWZ(r, kc));
                    bb[g*2+0][0] = t4[0]; bb[g*2+0][1] = t4[2];
                    bb[g*2+1][0] = t4[1]; bb[g*2+1][1] = t4[3];
                }
                #pragma unroll
                for (int m = 0; m < 4; m++)
                    #pragma unroll
                    for (int nn = 0; nn < 4; nn++) {
                        float* a = acc[m][half * 4 + nn];
                        mma_hf(a, ah[m], bb[nn]);
                        mma_hf(a, al[m], bb[nn]);
                    }
            }
        }
    }

    const int qr = lane >> 2;
    const int qc = (lane & 3) * 2;

    #pragma unroll
    for (int m = 0; m < 4; m++) {
        #pragma unroll
        for (int n = 0; n < 8; n++) {
            const int row = m0 + wm + m * 16 + qr;
            const int col = n0 + wn + n * 8 + qc;
            float v0 = acc[m][n][0], v1 = acc[m][n][1];
            float v2 = acc[m][n][2], v3 = acc[m][n][3];
            if (bias) {
                const float b0 = __ldg(&bias[col]), b1 = __ldg(&bias[col + 1]);
                v0 += b0; v1 += b1; v2 += b0; v3 += b1;
            }
            if (RELU) {
                v0 = fmaxf(v0, 0.f); v1 = fmaxf(v1, 0.f);
                v2 = fmaxf(v2, 0.f); v3 = fmaxf(v3, 0.f);
            }
            const size_t o0 = zoff + (size_t)row * N + col;
            const size_t o1 = zoff + (size_t)(row + 8) * N + col;
            if (OUTMODE == 0) {
                *(float2*)(Cf + o0) = make_float2(v0, v1);
                *(float2*)(Cf + o1) = make_float2(v2, v3);
            } else if (OUTMODE == 1) {
                uint32_t h0, l0, h1, l1;
                split_pair_h(v0, v1, h0, l0);
                split_pair_h(v2, v3, h1, l1);
                *(uint32_t*)(Ch + o0) = h0;
                *(uint32_t*)(Cl + o0) = l0;
                *(uint32_t*)(Ch + o1) = h1;
                *(uint32_t*)(Cl + o1) = l1;
            } else {
                HF2U p0; p0.h = __floats2half2_rn(v0, v1);
                HF2U p1; p1.h = __floats2half2_rn(v2, v3);
                *(uint32_t*)(Ch + o0) = p0.u;
                *(uint32_t*)(Ch + o1) = p1.u;
            }
        }
    }
}

// ===========================================================================
// fp32 flat -> bf16 hi/lo AND fp16 hi/lo (src feeds both Q/K (bf) and V (hf))
// ===========================================================================
__global__ __launch_bounds__(256)
void split4_k(const float4* __restrict__ in,
              uint2* __restrict__ obh, uint2* __restrict__ obl,
              uint2* __restrict__ ohh, uint2* __restrict__ ohl, int n4)
{
    int i = blockIdx.x * 256 + threadIdx.x;
    if (i >= n4) return;
    float4 v = in[i];
    uint2 bh, bl, hh, hl;
    split_pair(v.x, v.y, bh.x, bl.x);
    split_pair(v.z, v.w, bh.y, bl.y);
    split_pair_h(v.x, v.y, hh.x, hl.x);
    split_pair_h(v.z, v.w, hh.y, hl.y);
    obh[i] = bh; obl[i] = bl;
    ohh[i] = hh; ohl[i] = hl;
}

// ===========================================================================
// ALL weight transposes in ONE launch.
//  [0,2048):    Wq,Wk ExE fp32 -> transposed bf16 hi/lo
//  [2048,4096): Wv,Wo ExE fp32 -> transposed fp16 single
//  [4096,8192): W1 [E,FF] -> [FF,E] fp16 single
//  [8192,12288):W2 [FF,E] -> [E,FF] fp16 single
// ===========================================================================
__global__ __launch_bounds__(256)
void tsplit_all_k(const float* __restrict__ Wq, const float* __restrict__ Wk,
                  const float* __restrict__ Wv, const float* __restrict__ Wo,
                  const float* __restrict__ W1, const float* __restrict__ W2,
                  bf* __restrict__ Wqh, bf* __restrict__ Wql,
                  bf* __restrict__ Wkh, bf* __restrict__ Wkl,
                  hf* __restrict__ Wvt, hf* __restrict__ Wot,
                  hf* __restrict__ W1t, hf* __restrict__ W2t)
{
    __shared__ float t[32][33];
    const int idx = blockIdx.x;
    const int tx = threadIdx.x & 31, ty = threadIdx.x >> 5;

    const float* in; int R, C, mode; bf* oh = nullptr; bf* ol = nullptr; hf* of = nullptr;
    int r0, c0;
    if (idx < 2048) {
        const int w = idx >> 10, tt = idx & 1023;
        c0 = (tt & 31) * 32; r0 = (tt >> 5) * 32;
        R = E_DIM; C = E_DIM; mode = 0;
        if (w == 0) { in = Wq; oh = Wqh; ol = Wql; }
        else        { in = Wk; oh = Wkh; ol = Wkl; }
    } else if (idx < 4096) {
        const int w = (idx - 2048) >> 10, tt = idx & 1023;
        c0 = (tt & 31) * 32; r0 = (tt >> 5) * 32;
        R = E_DIM; C = E_DIM; mode = 1;
        if (w == 0) { in = Wv; of = Wvt; }
        else        { in = Wo; of = Wot; }
    } else if (idx < 8192) {
        const int tt = idx - 4096;
        c0 = (tt & 127) * 32; r0 = (tt >> 7) * 32;
        in = W1; R = E_DIM; C = FF_DIM; mode = 1; of = W1t;
    } else {
        const int tt = idx - 8192;
        c0 = (tt & 31) * 32; r0 = (tt >> 5) * 32;
        in = W2; R = FF_DIM; C = E_DIM; mode = 1; of = W2t;
    }

    #pragma unroll
    for (int i = 0; i < 4; i++)
        t[ty + i * 8][tx] = in[(size_t)(r0 + ty + i * 8) * C + c0 + tx];
    __syncthreads();
    #pragma unroll
    for (int i = 0; i < 4; i++) {
        const int orow = c0 + ty + i * 8, oc = r0 + tx;
        float v = t[tx][ty + i * 8];
        if (mode == 0) {
            bf h = __float2bfloat16(v);
            oh[(size_t)orow * R + oc] = h;
            ol[(size_t)orow * R + oc] = __float2bfloat16(v - __bfloat162float(h));
        } else {
            of[(size_t)orow * R + oc] = __float2half_rn(v);
        }
    }
}

// fp16 single [z][R][C] -> transposed [z][C][R]  (V)
__global__ __launch_bounds__(256)
void t_hf_k(const hf* __restrict__ in, hf* __restrict__ ot, int R, int C)
{
    __shared__ hf t[32][33];
    const size_t zo = (size_t)blockIdx.z * R * C;
    const int r0 = blockIdx.y * 32, c0 = blockIdx.x * 32;
    const int tx = threadIdx.x & 31, ty = threadIdx.x >> 5;
    #pragma unroll
    for (int i = 0; i < 4; i++)
        t[ty + i * 8][tx] = in[zo + (size_t)(r0 + ty + i * 8) * C + c0 + tx];
    __syncthreads();
    #pragma unroll
    for (int i = 0; i < 4; i++) {
        const int orow = c0 + ty + i * 8, oc = r0 + tx;
        ot[zo + (size_t)orow * R + oc] = t[tx][ty + i * 8];
    }
}

// ===========================================================================
// row softmax (2048 cols) -> fp16 hi/lo split (exact P for 2-MMA PV)
// ===========================================================================
__global__ __launch_bounds__(256)
void softmax_k(const float* __restrict__ S, hf* __restrict__ ph, hf* __restrict__ pl)
{
    const size_t rb = (size_t)blockIdx.x * SEQ;
    const int tid = threadIdx.x;
    __shared__ float red[256];
    float4 a = *(const float4*)(S + rb + tid * 8);
    float4 b = *(const float4*)(S + rb + tid * 8 + 4);
    float r[8] = {a.x, a.y, a.z, a.w, b.x, b.y, b.z, b.w};
    float m = -1e30f;
    #pragma unroll
    for (int i = 0; i < 8; i++) m = fmaxf(m, r[i]);
    red[tid] = m; __syncthreads();
    #pragma unroll
    for (int s = 128; s > 0; s >>= 1) { if (tid < s) red[tid] = fmaxf(red[tid], red[tid + s]); __syncthreads(); }
    m = red[0]; __syncthreads();
    float sum = 0.f;
    #pragma unroll
    for (int i = 0; i < 8; i++) { r[i] = __expf(r[i] - m); sum += r[i]; }
    red[tid] = sum; __syncthreads();
    #pragma unroll
    for (int s = 128; s > 0; s >>= 1) { if (tid < s) red[tid] += red[tid + s]; __syncthreads(); }
    const float inv = 1.f / red[0];
    uint32_t hp[4], lp[4];
    #pragma unroll
    for (int q = 0; q < 4; q++) split_pair_h(r[2*q] * inv, r[2*q+1] * inv, hp[q], lp[q]);
    *(uint4*)(ph + rb + tid * 8) = make_uint4(hp[0], hp[1], hp[2], hp[3]);
    *(uint4*)(pl + rb + tid * 8) = make_uint4(lp[0], lp[1], lp[2], lp[3]);
}

// ===========================================================================
// out = LN(a+b)*g + beta  (+ optional fp16 hi/lo split emit for FFN)
// ===========================================================================
template<bool WSPLIT>
__global__ __launch_bounds__(256)
void add_ln_k(const float* __restrict__ a, const float* __restrict__ b,
              const float* __restrict__ g, const float* __restrict__ beta,
              float* __restrict__ out, hf* __restrict__ oh, hf* __restrict__ ol)
{
    const size_t base = (size_t)blockIdx.x * E_DIM;
    const int tid = threadIdx.x, c = tid * 4;
    __shared__ float r1[256], r2[256];
    float4 va = *(const float4*)(a + base + c);
    float4 vb = *(const float4*)(b + base + c);
    float v[4] = {va.x + vb.x, va.y + vb.y, va.z + vb.z, va.w + vb.w};
    float s = 0.f, sq = 0.f;
    #pragma unroll
    for (int i = 0; i < 4; i++) { s += v[i]; sq += v[i] * v[i]; }
    r1[tid] = s; r2[tid] = sq; __syncthreads();
    #pragma unroll
    for (int st = 128; st > 0; st >>= 1) {
        if (tid < st) { r1[tid] += r1[tid + st]; r2[tid] += r2[tid + st]; }
        __syncthreads();
    }
    const float mu = r1[0] * (1.f / E_DIM);
    const float inv = rsqrtf(r2[0] * (1.f / E_DIM) - mu * mu + EPSV);
    float4 g4 = *(const float4*)(g + c);
    float4 b4 = *(const float4*)(beta + c);
    float o[4] = {(v[0]-mu)*inv*g4.x + b4.x, (v[1]-mu)*inv*g4.y + b4.y,
                  (v[2]-mu)*inv*g4.z + b4.z, (v[3]-mu)*inv*g4.w + b4.w};
    *(float4*)(out + base + c) = make_float4(o[0], o[1], o[2], o[3]);
    if (WSPLIT) {
        uint2 h, l;
        split_pair_h(o[0], o[1], h.x, l.x);
        split_pair_h(o[2], o[3], h.y, l.y);
        *(uint2*)(oh + base + c) = h;
        *(uint2*)(ol + base + c) = l;
    }
}

// ===========================================================================
// Host
// ===========================================================================
extern "C" void kernel_launch(void* const* d_in, const int* in_sizes, int n_in,
                              void* d_out, int out_size)
{
    (void)in_sizes; (void)n_in; (void)out_size;
    const float* src = (const float*)d_in[0];
    const float* Wq = (const float*)d_in[1];  const float* bq = (const float*)d_in[2];
    const float* Wk = (const float*)d_in[3];  const float* bk = (const float*)d_in[4];
    const float* Wv = (const float*)d_in[5];  const float* bv = (const float*)d_in[6];
    const float* Wo = (const float*)d_in[7];  const float* bo = (const float*)d_in[8];
    const float* W1 = (const float*)d_in[9];  const float* b1 = (const float*)d_in[10];
    const float* W2 = (const float*)d_in[11]; const float* b2 = (const float*)d_in[12];
    const float* g1 = (const float*)d_in[13]; const float* be1 = (const float*)d_in[14];
    const float* g2 = (const float*)d_in[15]; const float* be2 = (const float*)d_in[16];
    float* out = (float*)d_out;

    unsigned char* base = nullptr;
    cudaGetSymbolAddress((void**)&base, g_buf);
    size_t cur = 0;
    auto carve = [&](size_t bytes) { unsigned char* p = base + cur; cur += (bytes + 255) & ~(size_t)255; return p; };

    const size_t RE = (size_t)NROWS * E_DIM, RFF = (size_t)NROWS * FF_DIM;
    const size_t SS = (size_t)NB * SEQ * SEQ;
    const size_t WEE = (size_t)E_DIM * E_DIM, WEF = (size_t)E_DIM * FF_DIM;

    float* S_  = (float*)carve(SS * 4);
    float* tmp = (float*)carve(RE * 4);
    float* x   = (float*)carve(RE * 4);
    bf* srch = (bf*)carve(RE*2);  bf* srcl = (bf*)carve(RE*2);
    hf* srfh = (hf*)carve(RE*2);  hf* srfl = (hf*)carve(RE*2);
    bf* Qh = (bf*)carve(RE*2);    bf* Ql = (bf*)carve(RE*2);
    bf* Kh = (bf*)carve(RE*2);    bf* Kl = (bf*)carve(RE*2);
    hf* V_ = (hf*)carve(RE*2);
    hf* Vt = (hf*)carve(RE*2);
    hf* Ph = (hf*)carve(SS*2);    hf* Pl = (hf*)carve(SS*2);
    hf* ath = (hf*)carve(RE*2);   hf* atl = (hf*)carve(RE*2);
    hf* xh = (hf*)carve(RE*2);    hf* xl = (hf*)carve(RE*2);
    hf* ffh = (hf*)carve(RFF*2);  hf* ffl = (hf*)carve(RFF*2);
    bf* Wqh = (bf*)carve(WEE*2);  bf* Wql = (bf*)carve(WEE*2);
    bf* Wkh = (bf*)carve(WEE*2);  bf* Wkl = (bf*)carve(WEE*2);
    hf* Wvt = (hf*)carve(WEE*2);
    hf* Wot = (hf*)carve(WEE*2);
    hf* W1t = (hf*)carve(WEF*2);
    hf* W2t = (hf*)carve(WEF*2);

    cudaFuncSetAttribute(mma_gemm<false>, cudaFuncAttributeMaxDynamicSharedMemorySize, SMEM_GEMM);
    cudaFuncSetAttribute(qk_gemm,         cudaFuncAttributeMaxDynamicSharedMemorySize, SMEM_GEMM);
    cudaFuncSetAttribute(f16_gemm<0,false>, cudaFuncAttributeMaxDynamicSharedMemorySize, SMEM_F16);
    cudaFuncSetAttribute(f16_gemm<1,false>, cudaFuncAttributeMaxDynamicSharedMemorySize, SMEM_F16);
    cudaFuncSetAttribute(f16_gemm<1,true >, cudaFuncAttributeMaxDynamicSharedMemorySize, SMEM_F16);
    cudaFuncSetAttribute(f16_gemm<2,false>, cudaFuncAttributeMaxDynamicSharedMemorySize, SMEM_F16);

    const dim3 b256(256);
    // Launch order: profiled index 5 = my launch #3 (scores GEMM).
    // 0: all weight transposes
    tsplit_all_k<<<12288, b256>>>(Wq, Wk, Wv, Wo, W1, W2,
                                  Wqh, Wql, Wkh, Wkl, Wvt, Wot, W1t, W2t);
    // 1: src split (bf16 + fp16 pairs)
    split4_k<<<(int)(RE/4/256), b256>>>((const float4*)src,
        (uint2*)srch, (uint2*)srcl, (uint2*)srfh, (uint2*)srfl, (int)(RE/4));
    // 2: fused Q/K projections (bf16 3-MMA)
    qk_gemm<<<dim3(E_DIM/BN, NROWS/BM, 2), b256, SMEM_GEMM>>>(
        srch, srcl, Wqh, Wql, Wkh, Wkl, bq, bk, Qh, Ql, Kh, Kl);
    // 3: scores  S_b = Q_b @ K_b^T   <-- ncu capture target
    mma_gemm<false><<<dim3(SEQ/BN, SEQ/BM, NB), b256, SMEM_GEMM>>>(
        Qh, Ql, Kh, Kl, nullptr, S_, nullptr, nullptr, SEQ, E_DIM,
        (size_t)SEQ*E_DIM, (size_t)SEQ*E_DIM, (size_t)SEQ*SEQ);
    // 4: V projection (fp16 2-MMA, fp16 single out)
    f16_gemm<2,false><<<dim3(E_DIM/BN, NROWS/BM, 1), b256, SMEM_F16>>>(
        srfh, srfl, Wvt, bv, nullptr, V_, nullptr, E_DIM, E_DIM, 0, 0, 0);
    // 5: V transpose per batch [S,E] -> [E,S]
    t_hf_k<<<dim3(E_DIM/32, SEQ/32, NB), b256>>>(V_, Vt, SEQ, E_DIM);
    // 6: softmax -> fp16 split P
    softmax_k<<<NROWS, b256>>>(S_, Ph, Pl);
    // 7: attn = P_b @ V_b (fp16 2-MMA, fp16 split out)
    f16_gemm<1,false><<<dim3(E_DIM/BN, SEQ/BM, NB), b256, SMEM_F16>>>(
        Ph, Pl, Vt, nullptr, nullptr, ath, atl, E_DIM, SEQ,
        (size_t)SEQ*SEQ, (size_t)E_DIM*SEQ, (size_t)SEQ*E_DIM);
    // 8: O projection (fp16 2-MMA, fp32 out)
    f16_gemm<0,false><<<dim3(E_DIM/BN, NROWS/BM, 1), b256, SMEM_F16>>>(
        ath, atl, Wot, bo, tmp, nullptr, nullptr, E_DIM, E_DIM, 0, 0, 0);
    // 9: LN1 -> x (+ fp16 split)
    add_ln_k<true><<<NROWS, b256>>>(src, tmp, g1, be1, x, xh, xl);
    // 10: FFN1 (fp16 2-MMA, relu, fp16 split out)
    f16_gemm<1,true><<<dim3(FF_DIM/BN, NROWS/BM, 1), b256, SMEM_F16>>>(
        xh, xl, W1t, b1, nullptr, ffh, ffl, FF_DIM, E_DIM, 0, 0, 0);
    // 11: FFN2 (fp16 2-MMA, fp32 out)
    f16_gemm<0,false><<<dim3(E_DIM/BN, NROWS/BM, 1), b256, SMEM_F16>>>(
        ffh, ffl, W2t, b2, tmp, nullptr, nullptr, E_DIM, FF_DIM, 0, 0, 0);
    // 12: LN2 -> out
    add_ln_k<false><<<NROWS, b256>>>(x, tmp, g2, be2, out, nullptr, nullptr);
}